// round 3
// baseline (speedup 1.0000x reference)
#include <cuda_runtime.h>
#include <cuda_bf16.h>

// Problem constants
#define BB 2
#define SS 2048
#define DD 1024
#define HH 16
#define HS 64
// scale = sqrt(64) = 8  -> multiply scores by 0.125
#define INV_SCALE 0.125f

// Scratch for Q,K,V in [B,H,S,HS] layout (no cudaMalloc allowed)
__device__ float g_Q[BB * HH * SS * HS];
__device__ float g_K[BB * HH * SS * HS];
__device__ float g_V[BB * HH * SS * HS];

// ---------------------------------------------------------------------------
// QKV projection GEMM: out[m,n] = sum_k x[m,k] * W[n,k] + b[n]
// M = B*S = 4096, N = D = 1024, K = D = 1024
// Tile: 64x64, K-tile 16, 256 threads, 4x4 register tile per thread.
// Epilogue scatters into [B,H,S,HS] layout.
// ---------------------------------------------------------------------------
#define PM 64
#define PN 64
#define PK 16

__global__ __launch_bounds__(256) void qkv_kernel(
    const float* __restrict__ x,
    const float* __restrict__ Wq, const float* __restrict__ bq,
    const float* __restrict__ Wk, const float* __restrict__ bk,
    const float* __restrict__ Wv, const float* __restrict__ bv)
{
    const float* __restrict__ W;
    const float* __restrict__ bias;
    float* __restrict__ out;
    if (blockIdx.z == 0)      { W = Wq; bias = bq; out = g_Q; }
    else if (blockIdx.z == 1) { W = Wk; bias = bk; out = g_K; }
    else                      { W = Wv; bias = bv; out = g_V; }

    __shared__ __align__(16) float As[PK][PM];  // [k][m]
    __shared__ __align__(16) float Bs[PK][PN];  // [k][n]

    const int m0 = blockIdx.y * PM;
    const int n0 = blockIdx.x * PN;
    const int t  = threadIdx.x;
    const int lr = t >> 2;          // 0..63 : row within tile for loads
    const int lk = (t & 3) << 2;    // 0,4,8,12 : k offset for loads
    const int tx = t & 15;
    const int ty = t >> 4;

    float acc[4][4];
    #pragma unroll
    for (int i = 0; i < 4; i++)
        #pragma unroll
        for (int j = 0; j < 4; j++) acc[i][j] = 0.0f;

    const float* xrow = x + (long)(m0 + lr) * DD;
    const float* wrow = W + (long)(n0 + lr) * DD;

    for (int k0 = 0; k0 < DD; k0 += PK) {
        float4 av = *(const float4*)(xrow + k0 + lk);
        float4 bv4 = *(const float4*)(wrow + k0 + lk);
        __syncthreads();   // previous iteration's reads done
        As[lk + 0][lr] = av.x;  As[lk + 1][lr] = av.y;
        As[lk + 2][lr] = av.z;  As[lk + 3][lr] = av.w;
        Bs[lk + 0][lr] = bv4.x; Bs[lk + 1][lr] = bv4.y;
        Bs[lk + 2][lr] = bv4.z; Bs[lk + 3][lr] = bv4.w;
        __syncthreads();
        #pragma unroll
        for (int k = 0; k < PK; k++) {
            float4 a = *(const float4*)&As[k][ty << 2];
            float4 b = *(const float4*)&Bs[k][tx << 2];
            acc[0][0] += a.x * b.x; acc[0][1] += a.x * b.y;
            acc[0][2] += a.x * b.z; acc[0][3] += a.x * b.w;
            acc[1][0] += a.y * b.x; acc[1][1] += a.y * b.y;
            acc[1][2] += a.y * b.z; acc[1][3] += a.y * b.w;
            acc[2][0] += a.z * b.x; acc[2][1] += a.z * b.y;
            acc[2][2] += a.z * b.z; acc[2][3] += a.z * b.w;
            acc[3][0] += a.w * b.x; acc[3][1] += a.w * b.y;
            acc[3][2] += a.w * b.z; acc[3][3] += a.w * b.w;
        }
    }

    // Epilogue: add bias, scatter into [B,H,S,HS]
    #pragma unroll
    for (int i = 0; i < 4; i++) {
        const int m = m0 + (ty << 2) + i;
        const int b = m >> 11;          // m / S
        const int s = m & (SS - 1);     // m % S
        #pragma unroll
        for (int j = 0; j < 4; j++) {
            const int n  = n0 + (tx << 2) + j;
            const int h  = n >> 6;       // n / HS
            const int hs = n & (HS - 1); // n % HS
            const float v = acc[i][j] + __ldg(&bias[n]);
            out[(((long)(b * HH + h)) * SS + s) * HS + hs] = v;
        }
    }
}

// ---------------------------------------------------------------------------
// Flash attention (causal), fp32.
// Block handles 64 q-rows of one (b,h). 256 threads as 16x16, 4x4 per thread.
// smem: Qs[d][r], KP (K transposed [d][c], later aliased as P transposed [k][r]),
//       Vs[k][c]. 3 * 64*64*4 = 48KB exactly (static limit, graph-safe).
// ---------------------------------------------------------------------------
#define QT 64   // q rows per block
#define KT 64   // k cols per tile

__global__ __launch_bounds__(256) void attn_kernel(float* __restrict__ out)
{
    const int bh = blockIdx.y;        // 0..B*H-1
    const int jq = blockIdx.x;        // q-tile index 0..S/QT-1
    const int b  = bh >> 4;           // bh / H
    const int h  = bh & (HH - 1);     // bh % H

    const float* __restrict__ Q = g_Q + (long)bh * SS * HS;
    const float* __restrict__ K = g_K + (long)bh * SS * HS;
    const float* __restrict__ V = g_V + (long)bh * SS * HS;

    __shared__ __align__(16) float Qs[HS][QT];   // [d][r]
    __shared__ __align__(16) float KP[KT][KT];   // K^T [d][c] then P^T [k][r]
    __shared__ __align__(16) float Vs[KT][HS];   // [k][c]

    const int t  = threadIdx.x;
    const int tx = t & 15;
    const int ty = t >> 4;
    const int lr = t >> 2;            // 0..63 : row for loads
    const int ls = (t & 3) << 4;      // 0,16,32,48 : 16-float segment

    // Load Q tile transposed: Qs[d][r]
    {
        const float* qrow = Q + (long)(jq * QT + lr) * HS + ls;
        #pragma unroll
        for (int u = 0; u < 4; u++) {
            float4 v4 = *(const float4*)(qrow + u * 4);
            const int d = ls + u * 4;
            Qs[d + 0][lr] = v4.x; Qs[d + 1][lr] = v4.y;
            Qs[d + 2][lr] = v4.z; Qs[d + 3][lr] = v4.w;
        }
    }

    float m_i[4], l_i[4];
    float oacc[4][4];
    #pragma unroll
    for (int i = 0; i < 4; i++) {
        m_i[i] = -1e30f; l_i[i] = 0.0f;
        #pragma unroll
        for (int j = 0; j < 4; j++) oacc[i][j] = 0.0f;
    }

    const int r0g = jq * QT + (ty << 2);  // global q row base for this thread

    for (int jt = 0; jt <= jq; jt++) {
        const int k0 = jt * KT;
        __syncthreads();  // previous iteration's KP/Vs reads finished

        // Load K tile transposed KP[d][c], V tile natural Vs[k][c]
        {
            const float* krow = K + (long)(k0 + lr) * HS + ls;
            const float* vrow = V + (long)(k0 + lr) * HS + ls;
            #pragma unroll
            for (int u = 0; u < 4; u++) {
                float4 kv = *(const float4*)(krow + u * 4);
                const int d = ls + u * 4;
                KP[d + 0][lr] = kv.x; KP[d + 1][lr] = kv.y;
                KP[d + 2][lr] = kv.z; KP[d + 3][lr] = kv.w;
                float4 vv = *(const float4*)(vrow + u * 4);
                *(float4*)&Vs[lr][ls + u * 4] = vv;
            }
        }
        __syncthreads();

        // Scores s[4][4] = Q . K  (inner dim = HS)
        float s[4][4];
        #pragma unroll
        for (int i = 0; i < 4; i++)
            #pragma unroll
            for (int j = 0; j < 4; j++) s[i][j] = 0.0f;
        #pragma unroll
        for (int d = 0; d < HS; d++) {
            float4 a = *(const float4*)&Qs[d][ty << 2];
            float4 c = *(const float4*)&KP[d][tx << 2];
            s[0][0] += a.x * c.x; s[0][1] += a.x * c.y;
            s[0][2] += a.x * c.z; s[0][3] += a.x * c.w;
            s[1][0] += a.y * c.x; s[1][1] += a.y * c.y;
            s[1][2] += a.y * c.z; s[1][3] += a.y * c.w;
            s[2][0] += a.z * c.x; s[2][1] += a.z * c.y;
            s[2][2] += a.z * c.z; s[2][3] += a.z * c.w;
            s[3][0] += a.w * c.x; s[3][1] += a.w * c.y;
            s[3][2] += a.w * c.z; s[3][3] += a.w * c.w;
        }

        // Scale + causal mask (only on the diagonal tile)
        const bool diag = (jt == jq);
        #pragma unroll
        for (int i = 0; i < 4; i++) {
            const int qg = r0g + i;
            #pragma unroll
            for (int j = 0; j < 4; j++) {
                s[i][j] *= INV_SCALE;
                if (diag) {
                    const int kg = k0 + (tx << 2) + j;
                    if (kg > qg) s[i][j] = -1e30f;
                }
            }
        }

        // Online softmax: row max across 16-lane group (same ty)
        float p[4][4];
        float alpha[4];
        #pragma unroll
        for (int i = 0; i < 4; i++) {
            float mx = fmaxf(fmaxf(s[i][0], s[i][1]), fmaxf(s[i][2], s[i][3]));
            #pragma unroll
            for (int off = 8; off >= 1; off >>= 1)
                mx = fmaxf(mx, __shfl_xor_sync(0xffffffffu, mx, off, 16));
            const float newm = fmaxf(m_i[i], mx);
            alpha[i] = __expf(m_i[i] - newm);
            m_i[i] = newm;
            float rs = 0.0f;
            #pragma unroll
            for (int j = 0; j < 4; j++) {
                p[i][j] = __expf(s[i][j] - newm);
                rs += p[i][j];
            }
            #pragma unroll
            for (int off = 8; off >= 1; off >>= 1)
                rs += __shfl_xor_sync(0xffffffffu, rs, off, 16);
            l_i[i] = l_i[i] * alpha[i] + rs;
            #pragma unroll
            for (int j = 0; j < 4; j++) oacc[i][j] *= alpha[i];
        }

        __syncthreads();  // done reading KP as K^T

        // Store P transposed into KP: KP[k][r] = p  (k = key index, r = q row)
        #pragma unroll
        for (int i = 0; i < 4; i++)
            #pragma unroll
            for (int j = 0; j < 4; j++)
                KP[(tx << 2) + j][(ty << 2) + i] = p[i][j];
        __syncthreads();

        // O += P @ V : inner dim = k (64)
        #pragma unroll
        for (int k = 0; k < KT; k++) {
            float4 a = *(const float4*)&KP[k][ty << 2];
            float4 c = *(const float4*)&Vs[k][tx << 2];
            oacc[0][0] += a.x * c.x; oacc[0][1] += a.x * c.y;
            oacc[0][2] += a.x * c.z; oacc[0][3] += a.x * c.w;
            oacc[1][0] += a.y * c.x; oacc[1][1] += a.y * c.y;
            oacc[1][2] += a.y * c.z; oacc[1][3] += a.y * c.w;
            oacc[2][0] += a.z * c.x; oacc[2][1] += a.z * c.y;
            oacc[2][2] += a.z * c.z; oacc[2][3] += a.z * c.w;
            oacc[3][0] += a.w * c.x; oacc[3][1] += a.w * c.y;
            oacc[3][2] += a.w * c.z; oacc[3][3] += a.w * c.w;
        }
    }

    // Epilogue: normalize by l and write out[b, q, h*HS + c]
    #pragma unroll
    for (int i = 0; i < 4; i++) {
        const int q = r0g + i;
        const float inv_l = 1.0f / l_i[i];
        #pragma unroll
        for (int j = 0; j < 4; j++) {
            const int c = (tx << 2) + j;
            out[((long)(b * SS + q)) * DD + h * HS + c] = oacc[i][j] * inv_l;
        }
    }
}

extern "C" void kernel_launch(void* const* d_in, const int* in_sizes, int n_in,
                              void* d_out, int out_size)
{
    const float* x  = (const float*)d_in[0];
    const float* Wq = (const float*)d_in[1];
    const float* bq = (const float*)d_in[2];
    const float* Wk = (const float*)d_in[3];
    const float* bk = (const float*)d_in[4];
    const float* Wv = (const float*)d_in[5];
    const float* bv = (const float*)d_in[6];
    float* out = (float*)d_out;

    dim3 gproj(DD / PN, (BB * SS) / PM, 3);   // 16 x 64 x 3
    qkv_kernel<<<gproj, 256>>>(x, Wq, bq, Wk, bk, Wv, bv);

    dim3 gattn(SS / QT, BB * HH);             // 32 x 32
    attn_kernel<<<gattn, 256>>>(out);
}

// round 4
// speedup vs baseline: 1.3304x; 1.3304x over previous
#include <cuda_runtime.h>
#include <cuda_bf16.h>
#include <cstdint>

// Problem constants
#define BB 2
#define SS 2048
#define DD 1024
#define HH 16
#define HS 64
// scale = sqrt(64) = 8  -> multiply scores by 0.125
#define INV_SCALE 0.125f

// Scratch for Q,K,V in [B,H,S,HS] layout (no cudaMalloc allowed)
__device__ float g_Q[BB * HH * SS * HS];
__device__ float g_K[BB * HH * SS * HS];
__device__ float g_V[BB * HH * SS * HS];

// ---------------------------------------------------------------------------
// QKV projection on tensor cores: out[m,n] = sum_k x[m,k]*W[n,k] + b[n]
// M = 4096, N = 1024, K = 1024.
// bf16x3 compensated MMA: x = hi + lo (both bf16); acc += hi*hi' + hi*lo' + lo*hi'
// Block tile 128x128, BK=32 (bf16 elems), 256 threads = 8 warps (2m x 4n),
// warp tile 64x32 = 4x4 grid of m16n8k16 MMAs.
// smem rows padded to 20 u32 (40 halves): frag-load bank = (4g+t)%32, conflict-free.
// ---------------------------------------------------------------------------
#define BM 128
#define BN 128
#define BK 32
#define STR32 20   // u32 per smem row (16 data + 4 pad)

#define MMA_BF16(c, a, b) asm volatile( \
    "mma.sync.aligned.m16n8k16.row.col.f32.bf16.bf16.f32 " \
    "{%0,%1,%2,%3}, {%4,%5,%6,%7}, {%8,%9}, {%0,%1,%2,%3};\n" \
    : "+f"((c)[0]), "+f"((c)[1]), "+f"((c)[2]), "+f"((c)[3]) \
    : "r"((a)[0]), "r"((a)[1]), "r"((a)[2]), "r"((a)[3]), \
      "r"((b)[0]), "r"((b)[1]))

__device__ __forceinline__ uint32_t pack_bf16x2(float lo_elem, float hi_elem) {
    __nv_bfloat162 h = __floats2bfloat162_rn(lo_elem, hi_elem); // .x = first (low 16)
    uint32_t u;
    memcpy(&u, &h, 4);
    return u;
}

__global__ __launch_bounds__(256) void qkv_mma_kernel(
    const float* __restrict__ x,
    const float* __restrict__ Wq, const float* __restrict__ bq,
    const float* __restrict__ Wk, const float* __restrict__ bk,
    const float* __restrict__ Wv, const float* __restrict__ bv)
{
    const float* __restrict__ W;
    const float* __restrict__ bias;
    float* __restrict__ out;
    if (blockIdx.z == 0)      { W = Wq; bias = bq; out = g_Q; }
    else if (blockIdx.z == 1) { W = Wk; bias = bk; out = g_K; }
    else                      { W = Wv; bias = bv; out = g_V; }

    __shared__ uint32_t sA_hi[BM * STR32];
    __shared__ uint32_t sA_lo[BM * STR32];
    __shared__ uint32_t sB_hi[BN * STR32];
    __shared__ uint32_t sB_lo[BN * STR32];

    const int m0 = blockIdx.y * BM;
    const int n0 = blockIdx.x * BN;
    const int t    = threadIdx.x;
    const int wid  = t >> 5;
    const int lane = t & 31;
    const int wm = (wid & 1) * 64;    // warp m offset in tile
    const int wn = (wid >> 1) * 32;   // warp n offset in tile
    const int g  = lane >> 2;         // 0..7
    const int tq = lane & 3;          // 0..3

    // Loader mapping: thread t handles row (t>>1), half (t&1)*16 floats of k-chunk
    const int lrow  = t >> 1;
    const int lhalf = (t & 1) * 16;
    const float* xptr = x + (long)(m0 + lrow) * DD + lhalf;
    const float* wptr = W + (long)(n0 + lrow) * DD + lhalf;
    const int sbase = lrow * STR32 + (lhalf >> 1);

    float acc[4][4][4];
    #pragma unroll
    for (int mi = 0; mi < 4; mi++)
        #pragma unroll
        for (int ni = 0; ni < 4; ni++)
            #pragma unroll
            for (int c = 0; c < 4; c++) acc[mi][ni][c] = 0.0f;

    // Prefetch chunk 0
    float4 xa[4], wa[4];
    #pragma unroll
    for (int u = 0; u < 4; u++) {
        xa[u] = *(const float4*)(xptr + u * 4);
        wa[u] = *(const float4*)(wptr + u * 4);
    }

    for (int k0 = 0; k0 < DD; k0 += BK) {
        __syncthreads();   // previous compute done reading smem

        // Split current chunk into hi/lo and store to smem
        #pragma unroll
        for (int u = 0; u < 4; u++) {
            float xs[4] = {xa[u].x, xa[u].y, xa[u].z, xa[u].w};
            float ws[4] = {wa[u].x, wa[u].y, wa[u].z, wa[u].w};
            #pragma unroll
            for (int p = 0; p < 2; p++) {
                float f0 = xs[2 * p], f1 = xs[2 * p + 1];
                float h0 = __bfloat162float(__float2bfloat16_rn(f0));
                float h1 = __bfloat162float(__float2bfloat16_rn(f1));
                sA_hi[sbase + u * 2 + p] = pack_bf16x2(h0, h1);
                sA_lo[sbase + u * 2 + p] = pack_bf16x2(f0 - h0, f1 - h1);
                float g0 = ws[2 * p], g1 = ws[2 * p + 1];
                float e0 = __bfloat162float(__float2bfloat16_rn(g0));
                float e1 = __bfloat162float(__float2bfloat16_rn(g1));
                sB_hi[sbase + u * 2 + p] = pack_bf16x2(e0, e1);
                sB_lo[sbase + u * 2 + p] = pack_bf16x2(g0 - e0, g1 - e1);
            }
        }
        __syncthreads();

        // Prefetch next chunk (overlaps with MMA compute below)
        if (k0 + BK < DD) {
            #pragma unroll
            for (int u = 0; u < 4; u++) {
                xa[u] = *(const float4*)(xptr + k0 + BK + u * 4);
                wa[u] = *(const float4*)(wptr + k0 + BK + u * 4);
            }
        }

        // Two k16 slices per chunk
        #pragma unroll
        for (int kk = 0; kk < 2; kk++) {
            const int kc = kk * 8;
            uint32_t ah[4][4], al[4][4], bh[4][2], bl[4][2];
            #pragma unroll
            for (int mi = 0; mi < 4; mi++) {
                const int r = wm + mi * 16 + g;
                ah[mi][0] = sA_hi[r * STR32 + kc + tq];
                ah[mi][1] = sA_hi[(r + 8) * STR32 + kc + tq];
                ah[mi][2] = sA_hi[r * STR32 + kc + 4 + tq];
                ah[mi][3] = sA_hi[(r + 8) * STR32 + kc + 4 + tq];
                al[mi][0] = sA_lo[r * STR32 + kc + tq];
                al[mi][1] = sA_lo[(r + 8) * STR32 + kc + tq];
                al[mi][2] = sA_lo[r * STR32 + kc + 4 + tq];
                al[mi][3] = sA_lo[(r + 8) * STR32 + kc + 4 + tq];
            }
            #pragma unroll
            for (int ni = 0; ni < 4; ni++) {
                const int r = wn + ni * 8 + g;
                bh[ni][0] = sB_hi[r * STR32 + kc + tq];
                bh[ni][1] = sB_hi[r * STR32 + kc + 4 + tq];
                bl[ni][0] = sB_lo[r * STR32 + kc + tq];
                bl[ni][1] = sB_lo[r * STR32 + kc + 4 + tq];
            }
            #pragma unroll
            for (int mi = 0; mi < 4; mi++) {
                #pragma unroll
                for (int ni = 0; ni < 4; ni++) {
                    MMA_BF16(acc[mi][ni], ah[mi], bh[ni]);
                    MMA_BF16(acc[mi][ni], ah[mi], bl[ni]);
                    MMA_BF16(acc[mi][ni], al[mi], bh[ni]);
                }
            }
        }
    }

    // Epilogue: bias add, scatter into [B,H,S,HS]
    #pragma unroll
    for (int mi = 0; mi < 4; mi++) {
        #pragma unroll
        for (int ni = 0; ni < 4; ni++) {
            const int r0 = m0 + wm + mi * 16 + g;
            const int c0 = n0 + wn + ni * 8 + 2 * tq;
            #pragma unroll
            for (int c = 0; c < 4; c++) {
                const int row = r0 + (c >> 1) * 8;
                const int col = c0 + (c & 1);
                const int b  = row >> 11;
                const int s  = row & (SS - 1);
                const int h  = col >> 6;
                const int hs = col & (HS - 1);
                out[(((long)(b * HH + h)) * SS + s) * HS + hs] =
                    acc[mi][ni][c] + __ldg(&bias[col]);
            }
        }
    }
}

// ---------------------------------------------------------------------------
// Flash attention (causal), fp32 — unchanged from passing R2 kernel.
// ---------------------------------------------------------------------------
#define QT 64
#define KT 64

__global__ __launch_bounds__(256) void attn_kernel(float* __restrict__ out)
{
    const int bh = blockIdx.y;
    const int jq = blockIdx.x;
    const int b  = bh >> 4;
    const int h  = bh & (HH - 1);

    const float* __restrict__ Q = g_Q + (long)bh * SS * HS;
    const float* __restrict__ K = g_K + (long)bh * SS * HS;
    const float* __restrict__ V = g_V + (long)bh * SS * HS;

    __shared__ __align__(16) float Qs[HS][QT];
    __shared__ __align__(16) float KP[KT][KT];
    __shared__ __align__(16) float Vs[KT][HS];

    const int t  = threadIdx.x;
    const int tx = t & 15;
    const int ty = t >> 4;
    const int lr = t >> 2;
    const int ls = (t & 3) << 4;

    {
        const float* qrow = Q + (long)(jq * QT + lr) * HS + ls;
        #pragma unroll
        for (int u = 0; u < 4; u++) {
            float4 v4 = *(const float4*)(qrow + u * 4);
            const int d = ls + u * 4;
            Qs[d + 0][lr] = v4.x; Qs[d + 1][lr] = v4.y;
            Qs[d + 2][lr] = v4.z; Qs[d + 3][lr] = v4.w;
        }
    }

    float m_i[4], l_i[4];
    float oacc[4][4];
    #pragma unroll
    for (int i = 0; i < 4; i++) {
        m_i[i] = -1e30f; l_i[i] = 0.0f;
        #pragma unroll
        for (int j = 0; j < 4; j++) oacc[i][j] = 0.0f;
    }

    const int r0g = jq * QT + (ty << 2);

    for (int jt = 0; jt <= jq; jt++) {
        const int k0 = jt * KT;
        __syncthreads();

        {
            const float* krow = K + (long)(k0 + lr) * HS + ls;
            const float* vrow = V + (long)(k0 + lr) * HS + ls;
            #pragma unroll
            for (int u = 0; u < 4; u++) {
                float4 kv = *(const float4*)(krow + u * 4);
                const int d = ls + u * 4;
                KP[d + 0][lr] = kv.x; KP[d + 1][lr] = kv.y;
                KP[d + 2][lr] = kv.z; KP[d + 3][lr] = kv.w;
                float4 vv = *(const float4*)(vrow + u * 4);
                *(float4*)&Vs[lr][ls + u * 4] = vv;
            }
        }
        __syncthreads();

        float s[4][4];
        #pragma unroll
        for (int i = 0; i < 4; i++)
            #pragma unroll
            for (int j = 0; j < 4; j++) s[i][j] = 0.0f;
        #pragma unroll
        for (int d = 0; d < HS; d++) {
            float4 a = *(const float4*)&Qs[d][ty << 2];
            float4 c = *(const float4*)&KP[d][tx << 2];
            s[0][0] += a.x * c.x; s[0][1] += a.x * c.y;
            s[0][2] += a.x * c.z; s[0][3] += a.x * c.w;
            s[1][0] += a.y * c.x; s[1][1] += a.y * c.y;
            s[1][2] += a.y * c.z; s[1][3] += a.y * c.w;
            s[2][0] += a.z * c.x; s[2][1] += a.z * c.y;
            s[2][2] += a.z * c.z; s[2][3] += a.z * c.w;
            s[3][0] += a.w * c.x; s[3][1] += a.w * c.y;
            s[3][2] += a.w * c.z; s[3][3] += a.w * c.w;
        }

        const bool diag = (jt == jq);
        #pragma unroll
        for (int i = 0; i < 4; i++) {
            const int qg = r0g + i;
            #pragma unroll
            for (int j = 0; j < 4; j++) {
                s[i][j] *= INV_SCALE;
                if (diag) {
                    const int kg = k0 + (tx << 2) + j;
                    if (kg > qg) s[i][j] = -1e30f;
                }
            }
        }

        float p[4][4];
        float alpha[4];
        #pragma unroll
        for (int i = 0; i < 4; i++) {
            float mx = fmaxf(fmaxf(s[i][0], s[i][1]), fmaxf(s[i][2], s[i][3]));
            #pragma unroll
            for (int off = 8; off >= 1; off >>= 1)
                mx = fmaxf(mx, __shfl_xor_sync(0xffffffffu, mx, off, 16));
            const float newm = fmaxf(m_i[i], mx);
            alpha[i] = __expf(m_i[i] - newm);
            m_i[i] = newm;
            float rs = 0.0f;
            #pragma unroll
            for (int j = 0; j < 4; j++) {
                p[i][j] = __expf(s[i][j] - newm);
                rs += p[i][j];
            }
            #pragma unroll
            for (int off = 8; off >= 1; off >>= 1)
                rs += __shfl_xor_sync(0xffffffffu, rs, off, 16);
            l_i[i] = l_i[i] * alpha[i] + rs;
            #pragma unroll
            for (int j = 0; j < 4; j++) oacc[i][j] *= alpha[i];
        }

        __syncthreads();

        #pragma unroll
        for (int i = 0; i < 4; i++)
            #pragma unroll
            for (int j = 0; j < 4; j++)
                KP[(tx << 2) + j][(ty << 2) + i] = p[i][j];
        __syncthreads();

        #pragma unroll
        for (int k = 0; k < KT; k++) {
            float4 a = *(const float4*)&KP[k][ty << 2];
            float4 c = *(const float4*)&Vs[k][tx << 2];
            oacc[0][0] += a.x * c.x; oacc[0][1] += a.x * c.y;
            oacc[0][2] += a.x * c.z; oacc[0][3] += a.x * c.w;
            oacc[1][0] += a.y * c.x; oacc[1][1] += a.y * c.y;
            oacc[1][2] += a.y * c.z; oacc[1][3] += a.y * c.w;
            oacc[2][0] += a.z * c.x; oacc[2][1] += a.z * c.y;
            oacc[2][2] += a.z * c.z; oacc[2][3] += a.z * c.w;
            oacc[3][0] += a.w * c.x; oacc[3][1] += a.w * c.y;
            oacc[3][2] += a.w * c.z; oacc[3][3] += a.w * c.w;
        }
    }

    #pragma unroll
    for (int i = 0; i < 4; i++) {
        const int q = r0g + i;
        const float inv_l = 1.0f / l_i[i];
        #pragma unroll
        for (int j = 0; j < 4; j++) {
            const int c = (tx << 2) + j;
            out[((long)(b * SS + q)) * DD + h * HS + c] = oacc[i][j] * inv_l;
        }
    }
}

extern "C" void kernel_launch(void* const* d_in, const int* in_sizes, int n_in,
                              void* d_out, int out_size)
{
    const float* x  = (const float*)d_in[0];
    const float* Wq = (const float*)d_in[1];
    const float* bq = (const float*)d_in[2];
    const float* Wk = (const float*)d_in[3];
    const float* bk = (const float*)d_in[4];
    const float* Wv = (const float*)d_in[5];
    const float* bv = (const float*)d_in[6];
    float* out = (float*)d_out;

    dim3 gproj(DD / BN, (BB * SS) / BM, 3);   // 8 x 32 x 3
    qkv_mma_kernel<<<gproj, 256>>>(x, Wq, bq, Wk, bk, Wv, bv);

    dim3 gattn(SS / QT, BB * HH);             // 32 x 32
    attn_kernel<<<gattn, 256>>>(out);
}

// round 5
// speedup vs baseline: 2.1669x; 1.6287x over previous
#include <cuda_runtime.h>
#include <cuda_bf16.h>
#include <cstdint>

// Problem constants
#define BB 2
#define SS 2048
#define DD 1024
#define HH 16
#define HS 64
#define INV_SCALE 0.125f

// Q,K: [bh][s][hs] bf16 hi/lo.  V: TRANSPOSED [bh][hs][s] bf16 hi/lo.
__device__ __nv_bfloat16 g_Qh[BB * HH * SS * HS];
__device__ __nv_bfloat16 g_Ql[BB * HH * SS * HS];
__device__ __nv_bfloat16 g_Kh[BB * HH * SS * HS];
__device__ __nv_bfloat16 g_Kl[BB * HH * SS * HS];
__device__ __nv_bfloat16 g_Vh[BB * HH * SS * HS];
__device__ __nv_bfloat16 g_Vl[BB * HH * SS * HS];

#define MMA_BF16(c, a, b) asm volatile( \
    "mma.sync.aligned.m16n8k16.row.col.f32.bf16.bf16.f32 " \
    "{%0,%1,%2,%3}, {%4,%5,%6,%7}, {%8,%9}, {%0,%1,%2,%3};\n" \
    : "+f"((c)[0]), "+f"((c)[1]), "+f"((c)[2]), "+f"((c)[3]) \
    : "r"((a)[0]), "r"((a)[1]), "r"((a)[2]), "r"((a)[3]), \
      "r"((b)[0]), "r"((b)[1]))

__device__ __forceinline__ uint32_t pack_bf16x2(float lo_elem, float hi_elem) {
    __nv_bfloat162 h = __floats2bfloat162_rn(lo_elem, hi_elem); // .x = low 16 bits
    uint32_t u;
    memcpy(&u, &h, 4);
    return u;
}

// ---------------------------------------------------------------------------
// QKV projection (bf16x3 compensated MMA), epilogue emits bf16 hi/lo,
// V transposed. Block 128x128, BK=32, 256 thr = 8 warps.
// ---------------------------------------------------------------------------
#define BM 128
#define BN 128
#define BK 32
#define STR32 20

__global__ __launch_bounds__(256) void qkv_mma_kernel(
    const float* __restrict__ x,
    const float* __restrict__ Wq, const float* __restrict__ bq,
    const float* __restrict__ Wk, const float* __restrict__ bk,
    const float* __restrict__ Wv, const float* __restrict__ bv)
{
    const float* __restrict__ W;
    const float* __restrict__ bias;
    __nv_bfloat16* __restrict__ outh;
    __nv_bfloat16* __restrict__ outl;
    bool vtrans = false;
    if (blockIdx.z == 0)      { W = Wq; bias = bq; outh = g_Qh; outl = g_Ql; }
    else if (blockIdx.z == 1) { W = Wk; bias = bk; outh = g_Kh; outl = g_Kl; }
    else                      { W = Wv; bias = bv; outh = g_Vh; outl = g_Vl; vtrans = true; }

    __shared__ uint32_t sA_hi[BM * STR32];
    __shared__ uint32_t sA_lo[BM * STR32];
    __shared__ uint32_t sB_hi[BN * STR32];
    __shared__ uint32_t sB_lo[BN * STR32];

    const int m0 = blockIdx.y * BM;
    const int n0 = blockIdx.x * BN;
    const int t    = threadIdx.x;
    const int wid  = t >> 5;
    const int lane = t & 31;
    const int wm = (wid & 1) * 64;
    const int wn = (wid >> 1) * 32;
    const int g  = lane >> 2;
    const int tq = lane & 3;

    const int lrow  = t >> 1;
    const int lhalf = (t & 1) * 16;
    const float* xptr = x + (long)(m0 + lrow) * DD + lhalf;
    const float* wptr = W + (long)(n0 + lrow) * DD + lhalf;
    const int sbase = lrow * STR32 + (lhalf >> 1);

    float acc[4][4][4];
    #pragma unroll
    for (int mi = 0; mi < 4; mi++)
        #pragma unroll
        for (int ni = 0; ni < 4; ni++)
            #pragma unroll
            for (int c = 0; c < 4; c++) acc[mi][ni][c] = 0.0f;

    float4 xa[4], wa[4];
    #pragma unroll
    for (int u = 0; u < 4; u++) {
        xa[u] = *(const float4*)(xptr + u * 4);
        wa[u] = *(const float4*)(wptr + u * 4);
    }

    for (int k0 = 0; k0 < DD; k0 += BK) {
        __syncthreads();
        #pragma unroll
        for (int u = 0; u < 4; u++) {
            float xs[4] = {xa[u].x, xa[u].y, xa[u].z, xa[u].w};
            float ws[4] = {wa[u].x, wa[u].y, wa[u].z, wa[u].w};
            #pragma unroll
            for (int p = 0; p < 2; p++) {
                float f0 = xs[2 * p], f1 = xs[2 * p + 1];
                float h0 = __bfloat162float(__float2bfloat16_rn(f0));
                float h1 = __bfloat162float(__float2bfloat16_rn(f1));
                sA_hi[sbase + u * 2 + p] = pack_bf16x2(h0, h1);
                sA_lo[sbase + u * 2 + p] = pack_bf16x2(f0 - h0, f1 - h1);
                float g0 = ws[2 * p], g1 = ws[2 * p + 1];
                float e0 = __bfloat162float(__float2bfloat16_rn(g0));
                float e1 = __bfloat162float(__float2bfloat16_rn(g1));
                sB_hi[sbase + u * 2 + p] = pack_bf16x2(e0, e1);
                sB_lo[sbase + u * 2 + p] = pack_bf16x2(g0 - e0, g1 - e1);
            }
        }
        __syncthreads();

        if (k0 + BK < DD) {
            #pragma unroll
            for (int u = 0; u < 4; u++) {
                xa[u] = *(const float4*)(xptr + k0 + BK + u * 4);
                wa[u] = *(const float4*)(wptr + k0 + BK + u * 4);
            }
        }

        #pragma unroll
        for (int kk = 0; kk < 2; kk++) {
            const int kc = kk * 8;
            uint32_t ah[4][4], al[4][4], bh[4][2], bl[4][2];
            #pragma unroll
            for (int mi = 0; mi < 4; mi++) {
                const int r = wm + mi * 16 + g;
                ah[mi][0] = sA_hi[r * STR32 + kc + tq];
                ah[mi][1] = sA_hi[(r + 8) * STR32 + kc + tq];
                ah[mi][2] = sA_hi[r * STR32 + kc + 4 + tq];
                ah[mi][3] = sA_hi[(r + 8) * STR32 + kc + 4 + tq];
                al[mi][0] = sA_lo[r * STR32 + kc + tq];
                al[mi][1] = sA_lo[(r + 8) * STR32 + kc + tq];
                al[mi][2] = sA_lo[r * STR32 + kc + 4 + tq];
                al[mi][3] = sA_lo[(r + 8) * STR32 + kc + 4 + tq];
            }
            #pragma unroll
            for (int ni = 0; ni < 4; ni++) {
                const int r = wn + ni * 8 + g;
                bh[ni][0] = sB_hi[r * STR32 + kc + tq];
                bh[ni][1] = sB_hi[r * STR32 + kc + 4 + tq];
                bl[ni][0] = sB_lo[r * STR32 + kc + tq];
                bl[ni][1] = sB_lo[r * STR32 + kc + 4 + tq];
            }
            #pragma unroll
            for (int mi = 0; mi < 4; mi++) {
                #pragma unroll
                for (int ni = 0; ni < 4; ni++) {
                    MMA_BF16(acc[mi][ni], ah[mi], bh[ni]);
                    MMA_BF16(acc[mi][ni], ah[mi], bl[ni]);
                    MMA_BF16(acc[mi][ni], al[mi], bh[ni]);
                }
            }
        }
    }

    // Epilogue: bias, hi/lo split, scatter. Q/K: [bh][s][hs]; V: [bh][hs][s].
    #pragma unroll
    for (int mi = 0; mi < 4; mi++) {
        #pragma unroll
        for (int ni = 0; ni < 4; ni++) {
            const int r0 = m0 + wm + mi * 16 + g;
            const int c0 = n0 + wn + ni * 8 + 2 * tq;
            #pragma unroll
            for (int c = 0; c < 4; c++) {
                const int row = r0 + (c >> 1) * 8;
                const int col = c0 + (c & 1);
                const int b  = row >> 11;
                const int s  = row & (SS - 1);
                const int h  = col >> 6;
                const int hs = col & (HS - 1);
                const float v = acc[mi][ni][c] + __ldg(&bias[col]);
                __nv_bfloat16 vh = __float2bfloat16_rn(v);
                __nv_bfloat16 vl = __float2bfloat16_rn(v - __bfloat162float(vh));
                size_t idx;
                if (!vtrans) idx = ((size_t)(b * HH + h) * SS + s) * HS + hs;
                else         idx = ((size_t)(b * HH + h) * HS + hs) * SS + s;
                outh[idx] = vh;
                outl[idx] = vl;
            }
        }
    }
}

// ---------------------------------------------------------------------------
// Flash attention on tensor cores (bf16x3 compensated), causal.
// 128 thr = 4 warps; warp owns 16 q-rows; block 64 q-rows of one (b,h).
// smem K/V tiles strided 36 u32 (stride%32==4 -> bank==lane, conflict-free).
// S C-fragments re-map in-register to P A-fragments (no smem for P).
// ---------------------------------------------------------------------------
#define QT 64
#define KT 64
#define ASTR 36

__global__ __launch_bounds__(128) void attn_mma_kernel(float* __restrict__ out)
{
    const int bh = blockIdx.y;
    const int jq = (SS / QT - 1) - blockIdx.x;   // heavy tiles first
    const int b  = bh >> 4;
    const int h  = bh & (HH - 1);

    __shared__ uint32_t sK[2][64 * ASTR];  // [hi/lo][key][d-words]
    __shared__ uint32_t sV[2][64 * ASTR];  // [hi/lo][d][key-words]

    const int t    = threadIdx.x;
    const int wid  = t >> 5;
    const int lane = t & 31;
    const int g  = lane >> 2;
    const int tq = lane & 3;
    const int q0 = jq * QT + wid * 16;

    const uint32_t* Qh32 = (const uint32_t*)g_Qh + (size_t)bh * SS * (HS / 2);
    const uint32_t* Ql32 = (const uint32_t*)g_Ql + (size_t)bh * SS * (HS / 2);
    const uint32_t* Kh32 = (const uint32_t*)g_Kh + (size_t)bh * SS * (HS / 2);
    const uint32_t* Kl32 = (const uint32_t*)g_Kl + (size_t)bh * SS * (HS / 2);
    const uint32_t* Vh32 = (const uint32_t*)g_Vh + (size_t)bh * HS * (SS / 2);
    const uint32_t* Vl32 = (const uint32_t*)g_Vl + (size_t)bh * HS * (SS / 2);

    // Q fragments, register-resident for whole block
    uint32_t qh[4][4], ql[4][4];
    #pragma unroll
    for (int kt = 0; kt < 4; kt++) {
        const int w = 8 * kt + tq;
        qh[kt][0] = Qh32[(size_t)(q0 + g) * 32 + w];
        qh[kt][1] = Qh32[(size_t)(q0 + g + 8) * 32 + w];
        qh[kt][2] = Qh32[(size_t)(q0 + g) * 32 + w + 4];
        qh[kt][3] = Qh32[(size_t)(q0 + g + 8) * 32 + w + 4];
        ql[kt][0] = Ql32[(size_t)(q0 + g) * 32 + w];
        ql[kt][1] = Ql32[(size_t)(q0 + g + 8) * 32 + w];
        ql[kt][2] = Ql32[(size_t)(q0 + g) * 32 + w + 4];
        ql[kt][3] = Ql32[(size_t)(q0 + g + 8) * 32 + w + 4];
    }

    float oacc[8][4];
    #pragma unroll
    for (int j = 0; j < 8; j++)
        #pragma unroll
        for (int c = 0; c < 4; c++) oacc[j][c] = 0.0f;
    float mrow[2] = {-1e30f, -1e30f};
    float lrow[2] = {0.0f, 0.0f};

    // copy mapping: 128 threads, row = t>>1, 16-u32 segment = (t&1)*16
    const int cr = t >> 1;
    const int cs = (t & 1) * 16;

    for (int jt = 0; jt <= jq; jt++) {
        const int k0 = jt * KT;
        __syncthreads();
        {
            const uint4* skh = (const uint4*)(Kh32 + (size_t)(k0 + cr) * 32 + cs);
            const uint4* skl = (const uint4*)(Kl32 + (size_t)(k0 + cr) * 32 + cs);
            const uint4* svh = (const uint4*)(Vh32 + (size_t)cr * (SS / 2) + k0 / 2 + cs);
            const uint4* svl = (const uint4*)(Vl32 + (size_t)cr * (SS / 2) + k0 / 2 + cs);
            uint4* dkh = (uint4*)&sK[0][cr * ASTR + cs];
            uint4* dkl = (uint4*)&sK[1][cr * ASTR + cs];
            uint4* dvh = (uint4*)&sV[0][cr * ASTR + cs];
            uint4* dvl = (uint4*)&sV[1][cr * ASTR + cs];
            #pragma unroll
            for (int u = 0; u < 4; u++) {
                dkh[u] = skh[u];
                dkl[u] = skl[u];
                dvh[u] = svh[u];
                dvl[u] = svl[u];
            }
        }
        __syncthreads();

        // S = Q K^T (bf16x3)
        float s[8][4];
        #pragma unroll
        for (int j = 0; j < 8; j++)
            #pragma unroll
            for (int c = 0; c < 4; c++) s[j][c] = 0.0f;
        #pragma unroll
        for (int j = 0; j < 8; j++) {
            #pragma unroll
            for (int kt = 0; kt < 4; kt++) {
                const int base = (8 * j + g) * ASTR + 8 * kt + tq;
                uint32_t bhf[2], blf[2];
                bhf[0] = sK[0][base];     bhf[1] = sK[0][base + 4];
                blf[0] = sK[1][base];     blf[1] = sK[1][base + 4];
                MMA_BF16(s[j], qh[kt], bhf);
                MMA_BF16(s[j], ql[kt], bhf);
                MMA_BF16(s[j], qh[kt], blf);
            }
        }

        // scale + causal mask
        const bool diag = (jt == jq);
        #pragma unroll
        for (int j = 0; j < 8; j++) {
            #pragma unroll
            for (int c = 0; c < 4; c++) {
                s[j][c] *= INV_SCALE;
                if (diag) {
                    const int key = k0 + 8 * j + 2 * tq + (c & 1);
                    const int qg  = q0 + g + ((c >> 1) << 3);
                    if (key > qg) s[j][c] = -1e30f;
                }
            }
        }

        // online softmax (rows g and g+8; reduce over 4 tq lanes)
        float mx0 = -1e30f, mx1 = -1e30f;
        #pragma unroll
        for (int j = 0; j < 8; j++) {
            mx0 = fmaxf(mx0, fmaxf(s[j][0], s[j][1]));
            mx1 = fmaxf(mx1, fmaxf(s[j][2], s[j][3]));
        }
        mx0 = fmaxf(mx0, __shfl_xor_sync(0xffffffffu, mx0, 1, 4));
        mx0 = fmaxf(mx0, __shfl_xor_sync(0xffffffffu, mx0, 2, 4));
        mx1 = fmaxf(mx1, __shfl_xor_sync(0xffffffffu, mx1, 1, 4));
        mx1 = fmaxf(mx1, __shfl_xor_sync(0xffffffffu, mx1, 2, 4));
        const float nm0 = fmaxf(mrow[0], mx0);
        const float nm1 = fmaxf(mrow[1], mx1);
        const float al0 = __expf(mrow[0] - nm0);
        const float al1 = __expf(mrow[1] - nm1);
        mrow[0] = nm0; mrow[1] = nm1;
        float rs0 = 0.0f, rs1 = 0.0f;
        #pragma unroll
        for (int j = 0; j < 8; j++) {
            s[j][0] = __expf(s[j][0] - nm0);
            s[j][1] = __expf(s[j][1] - nm0);
            s[j][2] = __expf(s[j][2] - nm1);
            s[j][3] = __expf(s[j][3] - nm1);
            rs0 += s[j][0] + s[j][1];
            rs1 += s[j][2] + s[j][3];
        }
        rs0 += __shfl_xor_sync(0xffffffffu, rs0, 1, 4);
        rs0 += __shfl_xor_sync(0xffffffffu, rs0, 2, 4);
        rs1 += __shfl_xor_sync(0xffffffffu, rs1, 1, 4);
        rs1 += __shfl_xor_sync(0xffffffffu, rs1, 2, 4);
        lrow[0] = lrow[0] * al0 + rs0;
        lrow[1] = lrow[1] * al1 + rs1;
        #pragma unroll
        for (int j = 0; j < 8; j++) {
            oacc[j][0] *= al0; oacc[j][1] *= al0;
            oacc[j][2] *= al1; oacc[j][3] *= al1;
        }

        // P: S C-frag -> A-frag, hi/lo split in registers
        uint32_t ph[4][4], pl[4][4];
        #pragma unroll
        for (int kt = 0; kt < 4; kt++) {
            const int j0 = 2 * kt, j1 = 2 * kt + 1;
            float v00 = s[j0][0], v01 = s[j0][1], v02 = s[j0][2], v03 = s[j0][3];
            float v10 = s[j1][0], v11 = s[j1][1], v12 = s[j1][2], v13 = s[j1][3];
            float h00 = __bfloat162float(__float2bfloat16_rn(v00));
            float h01 = __bfloat162float(__float2bfloat16_rn(v01));
            float h02 = __bfloat162float(__float2bfloat16_rn(v02));
            float h03 = __bfloat162float(__float2bfloat16_rn(v03));
            float h10 = __bfloat162float(__float2bfloat16_rn(v10));
            float h11 = __bfloat162float(__float2bfloat16_rn(v11));
            float h12 = __bfloat162float(__float2bfloat16_rn(v12));
            float h13 = __bfloat162float(__float2bfloat16_rn(v13));
            ph[kt][0] = pack_bf16x2(h00, h01);
            ph[kt][1] = pack_bf16x2(h02, h03);
            ph[kt][2] = pack_bf16x2(h10, h11);
            ph[kt][3] = pack_bf16x2(h12, h13);
            pl[kt][0] = pack_bf16x2(v00 - h00, v01 - h01);
            pl[kt][1] = pack_bf16x2(v02 - h02, v03 - h03);
            pl[kt][2] = pack_bf16x2(v10 - h10, v11 - h11);
            pl[kt][3] = pack_bf16x2(v12 - h12, v13 - h13);
        }

        // O += P V (bf16x3); V^T in smem, j indexes d-tiles
        #pragma unroll
        for (int j = 0; j < 8; j++) {
            #pragma unroll
            for (int kt = 0; kt < 4; kt++) {
                const int base = (8 * j + g) * ASTR + 8 * kt + tq;
                uint32_t vh[2], vl[2];
                vh[0] = sV[0][base];     vh[1] = sV[0][base + 4];
                vl[0] = sV[1][base];     vl[1] = sV[1][base + 4];
                MMA_BF16(oacc[j], ph[kt], vh);
                MMA_BF16(oacc[j], pl[kt], vh);
                MMA_BF16(oacc[j], ph[kt], vl);
            }
        }
    }

    // Epilogue: normalize, write out[b, q, h*64 + d]
    const float il0 = 1.0f / lrow[0];
    const float il1 = 1.0f / lrow[1];
    #pragma unroll
    for (int j = 0; j < 8; j++) {
        const int col = h * HS + 8 * j + 2 * tq;
        const int qa = q0 + g;
        const int qb = q0 + g + 8;
        out[((size_t)(b * SS + qa)) * DD + col]     = oacc[j][0] * il0;
        out[((size_t)(b * SS + qa)) * DD + col + 1] = oacc[j][1] * il0;
        out[((size_t)(b * SS + qb)) * DD + col]     = oacc[j][2] * il1;
        out[((size_t)(b * SS + qb)) * DD + col + 1] = oacc[j][3] * il1;
    }
}

extern "C" void kernel_launch(void* const* d_in, const int* in_sizes, int n_in,
                              void* d_out, int out_size)
{
    const float* x  = (const float*)d_in[0];
    const float* Wq = (const float*)d_in[1];
    const float* bq = (const float*)d_in[2];
    const float* Wk = (const float*)d_in[3];
    const float* bk = (const float*)d_in[4];
    const float* Wv = (const float*)d_in[5];
    const float* bv = (const float*)d_in[6];
    float* out = (float*)d_out;

    dim3 gproj(DD / BN, (BB * SS) / BM, 3);   // 8 x 32 x 3
    qkv_mma_kernel<<<gproj, 256>>>(x, Wq, bq, Wk, bk, Wv, bv);

    dim3 gattn(SS / QT, BB * HH);             // 32 x 32
    attn_mma_kernel<<<gattn, 128>>>(out);
}